// round 2
// baseline (speedup 1.0000x reference)
#include <cuda_runtime.h>
#include <cstdint>

// Problem constants
#define BB 4
#define CC 128
#define HH 64
#define WW 128
#define DD 9            // 9 row-offsets x 9 col-offsets
#define CH 8            // channels per smem chunk
#define NCHUNK (CC / CH)
#define TROW 136        // 8 zero-pad floats + 128 data floats
#define TBUF (CH * DD * TROW)   // tgt floats per buffer  = 9792
#define SBUF (CH * WW)          // src floats per buffer  = 1024
#define BUFSZ (TBUF + SBUF)     // 10816 floats
#define SMEM_BYTES (2 * BUFSZ * 4)  // 86528 B
#define NTHREADS 288            // 9 warps (one per oy)

__device__ __forceinline__ void cp_async16(float* smem_dst, const float* gmem_src) {
    unsigned sm = (unsigned)__cvta_generic_to_shared(smem_dst);
    asm volatile("cp.async.cg.shared.global [%0], [%1], 16;\n" :: "r"(sm), "l"(gmem_src));
}
__device__ __forceinline__ void cp_commit() {
    asm volatile("cp.async.commit_group;\n" ::: "memory");
}
__device__ __forceinline__ void cp_wait1() {
    asm volatile("cp.async.wait_group 1;\n" ::: "memory");
}
__device__ __forceinline__ void cp_wait0() {
    asm volatile("cp.async.wait_group 0;\n" ::: "memory");
}

// Stage channel-chunk k into buffer buf. Layout per buffer (floats):
//   T[c][r][x], c<CH, r<DD, x<TROW  (x<8 is zero pad; x>=8 holds tgt[.., trow, x-8])
//   S[c][w]    at offset TBUF
__device__ __forceinline__ void prefetch_chunk(int k, int buf,
                                               const float* __restrict__ src,
                                               const float* __restrict__ tgt,
                                               int b, int h, float* smem, int tid) {
    const int c0 = k * CH;
    // CH * (DD tgt rows + 1 src row) * 32 float4 transfers
    #pragma unroll 1
    for (int i = tid; i < CH * (DD + 1) * 32; i += NTHREADS) {
        int c   = i / ((DD + 1) * 32);
        int rem = i - c * ((DD + 1) * 32);
        int r   = rem >> 5;      // 0..8 = tgt row, 9 = src row
        int f   = rem & 31;      // float4 index within the 128-float row
        if (r < DD) {
            int trow = h + r - 8;
            if (trow >= 0) {
                const float* g = tgt + (((size_t)(b * CC + c0 + c) * HH + trow) * WW) + f * 4;
                float* s = &smem[buf * BUFSZ + c * (DD * TROW) + r * TROW + 8 + f * 4];
                cp_async16(s, g);
            }
        } else {
            const float* g = src + (((size_t)(b * CC + c0 + c) * HH + h) * WW) + f * 4;
            float* s = &smem[buf * BUFSZ + TBUF + c * WW + f * 4];
            cp_async16(s, g);
        }
    }
}

__global__ __launch_bounds__(NTHREADS, 2)
void cost_volume_kernel(const float* __restrict__ src,
                        const float* __restrict__ tgt,
                        float* __restrict__ out) {
    extern __shared__ float smem[];
    const int bh   = blockIdx.x;
    const int b    = bh >> 6;    // / HH
    const int h    = bh & 63;
    const int tid  = threadIdx.x;
    const int warp = tid >> 5;   // oy in [0,9)
    const int lane = tid & 31;   // owns w = 4*lane .. 4*lane+3

    // Zero the 8-float left pads once for both buffers (2 float4 per row).
    // 2 bufs * CH * DD rows * 2 = 288 float4 = exactly NTHREADS
    {
        int i = tid;                         // < 288 always
        int buf  = i / (CH * DD * 2);
        int rem  = i - buf * (CH * DD * 2);
        int c    = rem / (DD * 2);
        int rem2 = rem - c * (DD * 2);
        int r    = rem2 >> 1;
        int f    = rem2 & 1;
        float4* p = (float4*)&smem[buf * BUFSZ + c * (DD * TROW) + r * TROW] + f;
        *p = make_float4(0.f, 0.f, 0.f, 0.f);
    }
    __syncthreads();

    const int  trow  = h + warp - 8;
    const bool valid = (trow >= 0);

    float acc[4][DD];
    #pragma unroll
    for (int wi = 0; wi < 4; wi++)
        #pragma unroll
        for (int d = 0; d < DD; d++) acc[wi][d] = 0.f;

    prefetch_chunk(0, 0, src, tgt, b, h, smem, tid);
    cp_commit();

    for (int k = 0; k < NCHUNK; k++) {
        if (k + 1 < NCHUNK) {
            prefetch_chunk(k + 1, (k + 1) & 1, src, tgt, b, h, smem, tid);
            cp_commit();
            cp_wait1();          // chunk k resident
        } else {
            cp_wait0();
        }
        __syncthreads();

        if (valid) {
            const float* Tb = &smem[(k & 1) * BUFSZ + warp * TROW + lane * 4];
            const float* Sb = &smem[(k & 1) * BUFSZ + TBUF + lane * 4];
            #pragma unroll
            for (int c = 0; c < CH; c++) {
                float4 s4 = *(const float4*)(Sb + c * WW);
                float4 t0 = *(const float4*)(Tb + c * (DD * TROW));
                float4 t1 = *(const float4*)(Tb + c * (DD * TROW) + 4);
                float4 t2 = *(const float4*)(Tb + c * (DD * TROW) + 8);
                float s[4] = {s4.x, s4.y, s4.z, s4.w};
                float t[12] = {t0.x, t0.y, t0.z, t0.w,
                               t1.x, t1.y, t1.z, t1.w,
                               t2.x, t2.y, t2.z, t2.w};
                #pragma unroll
                for (int wi = 0; wi < 4; wi++)
                    #pragma unroll
                    for (int d = 0; d < DD; d++)
                        acc[wi][d] = fmaf(s[wi], t[wi + d], acc[wi][d]);
            }
        }
        __syncthreads();   // buffer (k&1) free for prefetch of chunk k+2
    }

    // Epilogue: out[b, warp*9 + dj, h, 4*lane .. 4*lane+3]
    const size_t chan_stride = (size_t)HH * WW;
    float* op = out + ((size_t)(b * 81 + warp * DD) * HH + h) * WW + lane * 4;
    #pragma unroll
    for (int d = 0; d < DD; d++) {
        float4 v = valid ? make_float4(acc[0][d], acc[1][d], acc[2][d], acc[3][d])
                         : make_float4(0.f, 0.f, 0.f, 0.f);
        *(float4*)(op + (size_t)d * chan_stride) = v;
    }
}

extern "C" void kernel_launch(void* const* d_in, const int* in_sizes, int n_in,
                              void* d_out, int out_size) {
    const float* src = (const float*)d_in[0];
    const float* tgt = (const float*)d_in[1];
    float* out = (float*)d_out;

    cudaFuncSetAttribute(cost_volume_kernel,
                         cudaFuncAttributeMaxDynamicSharedMemorySize, SMEM_BYTES);

    cost_volume_kernel<<<BB * HH, NTHREADS, SMEM_BYTES>>>(src, tgt, out);
}

// round 4
// speedup vs baseline: 1.6258x; 1.6258x over previous
#include <cuda_runtime.h>
#include <cstdint>

// Problem constants
#define BB 4
#define CC 128
#define HH 64
#define WW 128
#define DD 9                 // 9 row-offsets (warps) x 9 col-offsets (accumulated)
#define CH 4                 // channels per chunk
#define NCHUNK (CC / CH)     // 32
#define TROW 136             // 8 zero-pad floats + 128 data floats
#define CHBUF (CH * TROW)    // 544 floats: one buffer (CH rows) per warp
#define WARPBUF (2 * CHBUF)  // 1088 floats: double-buffered per warp
#define NW 9
#define NTHREADS (NW * 32)   // 288
#define SMEM_FLOATS (NW * WARPBUF)  // 9792 floats = 39168 B

__device__ __forceinline__ void cp_async16(float* smem_dst, const float* gmem_src) {
    unsigned sm = (unsigned)__cvta_generic_to_shared(smem_dst);
    asm volatile("cp.async.cg.shared.global [%0], [%1], 16;\n" :: "r"(sm), "l"(gmem_src));
}
__device__ __forceinline__ void cp_commit() {
    asm volatile("cp.async.commit_group;\n" ::: "memory");
}
__device__ __forceinline__ void cp_wait1() {
    asm volatile("cp.async.wait_group 1;\n" ::: "memory");
}
__device__ __forceinline__ void cp_wait0() {
    asm volatile("cp.async.wait_group 0;\n" ::: "memory");
}

// Stage chunk k of this warp's tgt row into buffer buf.
// Pattern is fully regular: lane loads float4 #lane of channel u's row.
__device__ __forceinline__ void stage(const float* __restrict__ trowp, float* wbase,
                                      int k, int buf, int lane) {
    const float* g = trowp + (size_t)k * CH * HH * WW;
    float* s = wbase + buf * CHBUF + 8 + lane * 4;
    #pragma unroll
    for (int u = 0; u < CH; u++)
        cp_async16(s + u * TROW, g + (size_t)u * HH * WW);
    cp_commit();
}

__global__ __launch_bounds__(NTHREADS, 3)
void cost_volume_kernel(const float* __restrict__ src,
                        const float* __restrict__ tgt,
                        float* __restrict__ out) {
    __shared__ float smem[SMEM_FLOATS];
    const int bh   = blockIdx.x;
    const int b    = bh >> 6;        // / HH
    const int h    = bh & 63;
    const int tid  = threadIdx.x;
    const int warp = tid >> 5;       // oy in [0,9)
    const int lane = tid & 31;       // owns w = 4*lane .. 4*lane+3

    const int trow = h + warp - 8;
    float* op = out + ((size_t)(b * 81 + warp * DD) * HH + h) * WW + lane * 4;

    if (trow < 0) {
        // Invalid row-offset: output is zero. Write and retire the warp.
        float4 z = make_float4(0.f, 0.f, 0.f, 0.f);
        #pragma unroll
        for (int d = 0; d < DD; d++)
            *(float4*)(op + (size_t)d * HH * WW) = z;
        return;
    }

    float* wbase = smem + warp * WARPBUF;

    // Zero the 8-float left pads of all 2*CH rows of this warp (once).
    if (lane < 16) {
        int r = lane >> 1;           // 0..7 over (buf, c)
        int f = lane & 1;
        int buf = r >> 2, c = r & 3;
        *((float4*)(wbase + buf * CHBUF + c * TROW) + f) = make_float4(0.f, 0.f, 0.f, 0.f);
    }
    __syncwarp();

    // Per-warp global bases
    const float* trowp = tgt + ((size_t)(b * CC) * HH + trow) * WW + lane * 4;  // channel 0
    const float* srow  = src + ((size_t)(b * CC) * HH + h) * WW + lane * 4;

    float acc[4][DD];
    #pragma unroll
    for (int wi = 0; wi < 4; wi++)
        #pragma unroll
        for (int d = 0; d < DD; d++) acc[wi][d] = 0.f;

    stage(trowp, wbase, 0, 0, lane);

    #pragma unroll 2
    for (int k = 0; k < NCHUNK; k++) {
        const int buf = k & 1;
        if (k + 1 < NCHUNK) {
            stage(trowp, wbase, k + 1, buf ^ 1, lane);
            cp_wait1();                  // chunk k resident
        } else {
            cp_wait0();
        }
        __syncwarp();

        const float* Tb = wbase + buf * CHBUF + lane * 4;   // t[j] = Tb[c*TROW + j]
        const float* Sp = srow + (size_t)k * CH * HH * WW;
        #pragma unroll
        for (int c = 0; c < CH; c++) {
            float4 s4 = *(const float4*)(Sp + (size_t)c * HH * WW);   // LDG.128, L1-hot
            float4 t0 = *(const float4*)(Tb + c * TROW);
            float4 t1 = *(const float4*)(Tb + c * TROW + 4);
            float4 t2 = *(const float4*)(Tb + c * TROW + 8);
            float s[4]  = {s4.x, s4.y, s4.z, s4.w};
            float t[12] = {t0.x, t0.y, t0.z, t0.w,
                           t1.x, t1.y, t1.z, t1.w,
                           t2.x, t2.y, t2.z, t2.w};
            #pragma unroll
            for (int wi = 0; wi < 4; wi++)
                #pragma unroll
                for (int d = 0; d < DD; d++)
                    acc[wi][d] = fmaf(s[wi], t[wi + d], acc[wi][d]);
        }
        __syncwarp();   // lanes converged before next stage overwrites buf
    }

    // Epilogue: out[b, warp*9 + dj, h, 4*lane .. 4*lane+3]
    #pragma unroll
    for (int d = 0; d < DD; d++) {
        *(float4*)(op + (size_t)d * HH * WW) =
            make_float4(acc[0][d], acc[1][d], acc[2][d], acc[3][d]);
    }
}

extern "C" void kernel_launch(void* const* d_in, const int* in_sizes, int n_in,
                              void* d_out, int out_size) {
    const float* src = (const float*)d_in[0];
    const float* tgt = (const float*)d_in[1];
    float* out = (float*)d_out;
    cost_volume_kernel<<<BB * HH, NTHREADS>>>(src, tgt, out);
}